// round 1
// baseline (speedup 1.0000x reference)
#include <cuda_runtime.h>

// RoIAlign, NCHW fp32, OUT 7x7, sampling_ratio 2, scale 0.25
// features: (2, 256, 200, 304), rois: (512, 5), out: (512, 256, 7, 7)

namespace {
constexpr int OUT_H = 7;
constexpr int OUT_W = 7;
constexpr int C     = 256;
constexpr int H     = 200;
constexpr int W     = 304;
constexpr int R     = 512;
constexpr float SCALE = 0.25f;

constexpr int WARPS_PER_BLOCK = 8;
constexpr int GROUPS          = 8;                           // gridDim.y
constexpr int WARPS_PER_ROI   = WARPS_PER_BLOCK * GROUPS;    // 64
constexpr int CH_PER_WARP     = C / WARPS_PER_ROI;           // 4
constexpr int PLANE           = H * W;                       // 60800
}

__global__ __launch_bounds__(WARPS_PER_BLOCK * 32)
void roi_align_kernel(const float* __restrict__ feat,
                      const float* __restrict__ rois,
                      float* __restrict__ out)
{
    const int r      = blockIdx.x;
    const int warpId = threadIdx.x >> 5;
    const int lane   = threadIdx.x & 31;
    const int wroi   = blockIdx.y * WARPS_PER_BLOCK + warpId;   // 0..63
    const int c0     = wroi * CH_PER_WARP;

    // Per-roi constants (uniform across warp; cheap redundant loads, L1/L2 hit)
    const float bf = rois[r * 5 + 0];
    const float x1 = rois[r * 5 + 1] * SCALE - 0.5f;
    const float y1 = rois[r * 5 + 2] * SCALE - 0.5f;
    const float x2 = rois[r * 5 + 3] * SCALE - 0.5f;
    const float y2 = rois[r * 5 + 4] * SCALE - 0.5f;
    const int   b  = (int)bf;

    const float bin_w = (x2 - x1) * (1.0f / OUT_W);
    const float bin_h = (y2 - y1) * (1.0f / OUT_H);

    // Lane -> sample mapping for one bin-row (oy):
    //   lanes 0..13  : y-sample g=0, x-samples sx=0..13
    //   lanes 14..27 : y-sample g=1, x-samples sx=0..13
    //   lanes 28..31 : idle (weights forced to 0)
    const int gy  = (lane >= 14) ? 1 : 0;
    const int sxl = lane - gy * 14;      // 0..13 for active lanes

    const float* planes = feat + ((size_t)b * C + c0) * PLANE;

    for (int oy = 0; oy < OUT_H; ++oy) {
        float w00 = 0.f, w01 = 0.f, w10 = 0.f, w11 = 0.f;
        int   off = 0, dX = 0, dYW = 0;

        if (lane < 28) {
            // match reference: y1 + (iy//G)*bin_h + (iy%G + 0.5)*bin_h/G
            float y = y1 + (float)oy * bin_h + ((float)gy + 0.5f) * bin_h * 0.5f;
            float x = x1 + (float)(sxl >> 1) * bin_w
                         + ((float)(sxl & 1) + 0.5f) * bin_w * 0.5f;

            bool valid = (y > -1.0f) && (y < (float)H) &&
                         (x > -1.0f) && (x < (float)W);

            float yc = fminf(fmaxf(y, 0.0f), (float)(H - 1));
            float xc = fminf(fmaxf(x, 0.0f), (float)(W - 1));
            int y0 = (int)floorf(yc);
            int x0 = (int)floorf(xc);
            int y1i = min(y0 + 1, H - 1);
            int x1i = min(x0 + 1, W - 1);
            float ly = yc - (float)y0;
            float lx = xc - (float)x0;
            float hy = 1.0f - ly;
            float hx = 1.0f - lx;
            float vf = valid ? 1.0f : 0.0f;

            w00 = hy * hx * vf;
            w01 = hy * lx * vf;
            w10 = ly * hx * vf;
            w11 = ly * lx * vf;
            off = y0 * W + x0;
            dX  = x1i - x0;            // 0 or 1
            dYW = (y1i - y0) * W;      // 0 or W
        }
        // idle lanes: off=0 => loads hit plane base (in bounds), weights 0

        #pragma unroll
        for (int cc = 0; cc < CH_PER_WARP; ++cc) {
            const float* q = planes + (size_t)cc * PLANE + off;
            float v00 = __ldg(q);
            float v01 = __ldg(q + dX);
            float v10 = __ldg(q + dYW);
            float v11 = __ldg(q + dYW + dX);
            float acc = w00 * v00 + w01 * v01 + w10 * v10 + w11 * v11;

            // reduce the 2x2 sample group for each output bin:
            // +14: sum the two y-samples; +1: sum the two x-samples
            acc += __shfl_down_sync(0xffffffffu, acc, 14);
            acc += __shfl_down_sync(0xffffffffu, acc, 1);

            if (lane < 14 && (lane & 1) == 0) {
                out[(((size_t)r * C + (c0 + cc)) * OUT_H + oy) * OUT_W + (lane >> 1)]
                    = acc * 0.25f;
            }
        }
    }
}

extern "C" void kernel_launch(void* const* d_in, const int* in_sizes, int n_in,
                              void* d_out, int out_size)
{
    const float* feat = (const float*)d_in[0];
    const float* rois = (const float*)d_in[1];
    float*       out  = (float*)d_out;

    dim3 grid(R, GROUPS);
    dim3 block(WARPS_PER_BLOCK * 32);
    roi_align_kernel<<<grid, block>>>(feat, rois, out);
}